// round 14
// baseline (speedup 1.0000x reference)
#include <cuda_runtime.h>

#define BB 4
#define DD 4
#define HH 768
#define WW 768
#define RR 4

// Prefetch one padded row: center float4 + predicated halo scalars (lanes 0/31).
__device__ __forceinline__ void prefetch_row(const float* __restrict__ row, int w0,
                                             int wl, int wr, int lane,
                                             float4& c4, float& lv, float& rv) {
    c4 = *reinterpret_cast<const float4*>(row + w0);
    if (lane == 0)  lv = __ldg(row + wl);
    if (lane == 31) rv = __ldg(row + wr);
}

// Consume a prefetched row into the 6-value window segment (SHFL halo exchange).
__device__ __forceinline__ void consume_row(float4 c4, float plv, float prv, int lane,
                                            float v[6]) {
    float lv = __shfl_up_sync(0xffffffffu, c4.w, 1);
    float rv = __shfl_down_sync(0xffffffffu, c4.x, 1);
    if (lane == 0)  lv = plv;
    if (lane == 31) rv = prv;
    v[0] = lv; v[1] = c4.x; v[2] = c4.y; v[3] = c4.z; v[4] = c4.w; v[5] = rv;
}

__global__ __launch_bounds__(192, 3)
void cqi3d_kernel(const float* __restrict__ x, float* __restrict__ out) {
    const int tid  = threadIdx.x;
    const int lane = tid & 31;
    const int w0   = tid * 4;
    const int hb   = (blockIdx.x % (HH / RR)) * RR;
    const int p    = blockIdx.x / (HH / RR);
    const int d    = p % DD;
    const int b    = p / DD;

    const size_t HW = (size_t)HH * WW;
    const size_t sp = (size_t)hb * WW + w0;
    float* o0 = out + ((size_t)(b * 3 + 0) * DD + d) * HW + sp;
    float* o1 = out + ((size_t)(b * 3 + 1) * DD + d) * HW + sp;
    float* o2 = out + ((size_t)(b * 3 + 2) * DD + d) * HW + sp;
    float* oy = out + (size_t)3 * BB * DD * HW + ((size_t)(b * DD + d)) * HW + sp;

    // ---- trivial path: d = 0 or D-1 can never be a strict 26-neighbour maximum
    // (replicate padding makes the clamped d-neighbour equal x0): offsets are 0,
    // y_max = x exactly. Streaming copy + constant coords.
    if (d == 0 || d == DD - 1) {
        const float* pl1 = x + ((size_t)(b * DD + d) * HH) * WW + sp;
        const float fd = (float)d;
        const float4 c0q = make_float4(fd, fd, fd, fd);
        const float4 c1q = make_float4((float)w0, (float)(w0 + 1), (float)(w0 + 2), (float)(w0 + 3));
        #pragma unroll
        for (int r = 0; r < RR; r++) {
            const float fh = (float)(hb + r);
            float4 xv = *reinterpret_cast<const float4*>(pl1 + (size_t)r * WW);
            __stcs(reinterpret_cast<float4*>(o0 + (size_t)r * WW), c0q);
            __stcs(reinterpret_cast<float4*>(o1 + (size_t)r * WW), c1q);
            __stcs(reinterpret_cast<float4*>(o2 + (size_t)r * WW), make_float4(fh, fh, fh, fh));
            __stcs(reinterpret_cast<float4*>(oy + (size_t)r * WW), xv);
        }
        return;
    }

    // ---- stencil path: d in {1, 2}, all three d-planes are real (no clamping) ----
    const float* pl0 = x + ((size_t)(b * DD + (d - 1)) * HH) * WW;
    const float* pl1 = x + ((size_t)(b * DD + d      ) * HH) * WW;
    const float* pl2 = x + ((size_t)(b * DD + (d + 1)) * HH) * WW;

    const int wl = (w0 == 0) ? 0 : (w0 - 1);
    const int wr = (w0 + 4 >= WW) ? (WW - 1) : (w0 + 4);

    float v[3][3][6];   // [plane][slot][k]
    float rm9[3][6];    // per-slot 3-plane column max

    // prologue: fill slots 0 (row hb-1 clamped) and 1 (row hb)
    {
        const int ht = (hb == 0) ? 0 : (hb - 1);
        float4 c; float lv, rv;
        prefetch_row(pl0 + (size_t)ht * WW, w0, wl, wr, lane, c, lv, rv);
        consume_row(c, lv, rv, lane, v[0][0]);
        prefetch_row(pl1 + (size_t)ht * WW, w0, wl, wr, lane, c, lv, rv);
        consume_row(c, lv, rv, lane, v[1][0]);
        prefetch_row(pl2 + (size_t)ht * WW, w0, wl, wr, lane, c, lv, rv);
        consume_row(c, lv, rv, lane, v[2][0]);
        prefetch_row(pl0 + (size_t)hb * WW, w0, wl, wr, lane, c, lv, rv);
        consume_row(c, lv, rv, lane, v[0][1]);
        prefetch_row(pl1 + (size_t)hb * WW, w0, wl, wr, lane, c, lv, rv);
        consume_row(c, lv, rv, lane, v[1][1]);
        prefetch_row(pl2 + (size_t)hb * WW, w0, wl, wr, lane, c, lv, rv);
        consume_row(c, lv, rv, lane, v[2][1]);
        #pragma unroll
        for (int k = 0; k < 6; k++) {
            rm9[0][k] = fmaxf(fmaxf(v[0][0][k], v[1][0][k]), v[2][0][k]);
            rm9[1][k] = fmaxf(fmaxf(v[0][1][k], v[1][1][k]), v[2][1][k]);
        }
    }

    // prefetch row hb+1 (always interior: hb+1 <= HH-RR+1 < HH)
    float4 Pc[3]; float Plv[3], Prv[3];
    prefetch_row(pl0 + (size_t)(hb + 1) * WW, w0, wl, wr, lane, Pc[0], Plv[0], Prv[0]);
    prefetch_row(pl1 + (size_t)(hb + 1) * WW, w0, wl, wr, lane, Pc[1], Plv[1], Prv[1]);
    prefetch_row(pl2 + (size_t)(hb + 1) * WW, w0, wl, wr, lane, Pc[2], Plv[2], Prv[2]);

    #pragma unroll
    for (int r = 0; r < RR; r++) {
        const int st = r % 3;
        const int sm = (r + 1) % 3;
        const int sb = (r + 2) % 3;
        const int h  = hb + r;

        // consume prefetched row h+1 into slot sb
        consume_row(Pc[0], Plv[0], Prv[0], lane, v[0][sb]);
        consume_row(Pc[1], Plv[1], Prv[1], lane, v[1][sb]);
        consume_row(Pc[2], Plv[2], Prv[2], lane, v[2][sb]);
        #pragma unroll
        for (int k = 0; k < 6; k++)
            rm9[sb][k] = fmaxf(fmaxf(v[0][sb][k], v[1][sb][k]), v[2][sb][k]);

        // immediately issue next iteration's loads (row h+2, clamped) so they
        // overlap this iteration's NMS/solve/store
        if (r < RR - 1) {
            const int hn = (h + 2 >= HH) ? (HH - 1) : (h + 2);
            prefetch_row(pl0 + (size_t)hn * WW, w0, wl, wr, lane, Pc[0], Plv[0], Prv[0]);
            prefetch_row(pl1 + (size_t)hn * WW, w0, wl, wr, lane, Pc[1], Plv[1], Prv[1]);
            prefetch_row(pl2 + (size_t)hn * WW, w0, wl, wr, lane, Pc[2], Plv[2], Prv[2]);
        }

        // ---- NMS (separable): vm = vertical max of top/bottom slot maxima ----
        float vm[6];
        #pragma unroll
        for (int k = 0; k < 6; k++) vm[k] = fmaxf(rm9[st][k], rm9[sb][k]);

        bool nmsq[4];
        unsigned bal[4];
        #pragma unroll
        for (int j = 0; j < 4; j++) {
            const int c = j + 1;
            float nb = fmaxf(vm[c - 1], vm[c]);
            nb = fmaxf(nb, vm[c + 1]);
            nb = fmaxf(nb, rm9[sm][c - 1]);
            nb = fmaxf(nb, rm9[sm][c + 1]);
            nb = fmaxf(nb, fmaxf(v[0][sm][c], v[2][sm][c]));
            nb = fmaxf(nb, 0.0f);
            nmsq[j] = (v[1][sm][c] > nb);
            bal[j] = __ballot_sync(0xffffffffu, nmsq[j]);
        }

        // ---- shared row differences (CSE for gy/dxy and gs/dys/dxs) ----
        float diffbt[6], d20sm[6];
        #pragma unroll
        for (int k = 0; k < 6; k++) {
            diffbt[k] = v[1][sb][k] - v[1][st][k];
            d20sm[k]  = v[2][sm][k] - v[0][sm][k];
        }

        float oc0[4], oc1[4], oc2[4], oyv[4];
        const float fh = (float)h;

        #pragma unroll
        for (int j = 0; j < 4; j++) {
            const int c = j + 1;
            const float x0 = v[1][sm][c];

            if (bal[j]) {   // warp-uniform: at least one lane is a strict maximum
                const float gx = 0.5f * (v[1][sm][c + 1] - v[1][sm][c - 1]);
                const float gy = 0.5f * diffbt[c];
                const float gs = 0.5f * d20sm[c];

                const float dxx = v[1][sm][c + 1] + v[1][sm][c - 1] - 2.0f * x0;
                const float dyy = v[1][sb][c]     + v[1][st][c]     - 2.0f * x0;
                const float dss = v[2][sm][c]     + v[0][sm][c]     - 2.0f * x0;

                const float dxy =  0.25f * (diffbt[c + 1] - diffbt[c - 1]);
                const float dys = -0.25f * ((v[2][sb][c] - v[0][sb][c]) - (v[2][st][c] - v[0][st][c]));
                const float dxs = -0.25f * (d20sm[c + 1] - d20sm[c - 1]);

                const float cf00 = dyy * dss - dys * dys;
                const float cf01 = dxy * dss - dys * dxs;
                const float cf02 = dxy * dys - dyy * dxs;
                const float det  = dxx * cf00 - dxy * cf01 + dxs * cf02;
                const bool solved = (det != 0.0f);
                float inv;
                asm("rcp.approx.f32 %0, %1;" : "=f"(inv) : "f"(solved ? det : 1.0f));

                const float t0 = gy * dss - dys * gs;
                const float t1 = gy * dys - dyy * gs;
                const float t2 = dxy * gs - gy * dxs;

                const float sx = (gx  * cf00 - dxy * t0   + dxs * t1) * inv;
                const float sy = (dxx * t0   - gx  * cf01 + dxs * t2) * inv;
                const float ss = (-dxx * t1  - dxy * t2   + gx  * cf02) * inv;

                const bool valid = nmsq[j] && solved;
                const float amax = fmaxf(fmaxf(fabsf(sx), fabsf(sy)), fabsf(ss));
                const bool keep = valid && (amax <= 0.7f);

                oc0[j] = (float)d + (keep ? -ss : 0.0f);
                oc1[j] = (float)(w0 + j) + (keep ? -sx : 0.0f);
                oc2[j] = fh + (keep ? -sy : 0.0f);

                float ym = valid ? (x0 + 10.0f) : x0;
                if (keep) {
                    const float t = fmaf(gx, sx, fmaf(gy, sy, gs * ss));
                    ym = fmaf(-0.5f, t, ym);
                }
                oyv[j] = ym;
            } else {        // no maximum anywhere in this warp column: trivial output
                oc0[j] = (float)d;
                oc1[j] = (float)(w0 + j);
                oc2[j] = fh;
                oyv[j] = x0;
            }
        }

        __stcs(reinterpret_cast<float4*>(o0 + (size_t)r * WW), make_float4(oc0[0], oc0[1], oc0[2], oc0[3]));
        __stcs(reinterpret_cast<float4*>(o1 + (size_t)r * WW), make_float4(oc1[0], oc1[1], oc1[2], oc1[3]));
        __stcs(reinterpret_cast<float4*>(o2 + (size_t)r * WW), make_float4(oc2[0], oc2[1], oc2[2], oc2[3]));
        __stcs(reinterpret_cast<float4*>(oy + (size_t)r * WW), make_float4(oyv[0], oyv[1], oyv[2], oyv[3]));
    }
}

extern "C" void kernel_launch(void* const* d_in, const int* in_sizes, int n_in,
                              void* d_out, int out_size) {
    const float* x = (const float*)d_in[0];
    float* out = (float*)d_out;
    dim3 grid(BB * DD * (HH / RR));  // 3072 blocks
    dim3 block(192);
    cqi3d_kernel<<<grid, block>>>(x, out);
}

// round 17
// speedup vs baseline: 1.2268x; 1.2268x over previous
#include <cuda_runtime.h>

#define BB 4
#define DD 4
#define HH 768
#define WW 768
#define RR 4

// Load one padded row segment of 6 values: [w0-1, w0..w0+3, w0+4].
__device__ __forceinline__ void load_row6(const float* __restrict__ row, int w0, int lane,
                                          float v[6]) {
    float4 c4 = *reinterpret_cast<const float4*>(row + w0);
    float lv = __shfl_up_sync(0xffffffffu, c4.w, 1);
    float rv = __shfl_down_sync(0xffffffffu, c4.x, 1);
    if (lane == 0) {
        const int wl = (w0 == 0) ? 0 : (w0 - 1);
        lv = __ldg(row + wl);
    }
    if (lane == 31) {
        const int wr = (w0 + 4 >= WW) ? (WW - 1) : (w0 + 4);
        rv = __ldg(row + wr);
    }
    v[0] = lv; v[1] = c4.x; v[2] = c4.y; v[3] = c4.z; v[4] = c4.w; v[5] = rv;
}

__global__ __launch_bounds__(192, 4)
void cqi3d_kernel(const float* __restrict__ x, float* __restrict__ out) {
    const int tid  = threadIdx.x;
    const int lane = tid & 31;
    const int w0   = tid * 4;
    const int hb   = (blockIdx.x % (HH / RR)) * RR;
    const int p    = blockIdx.x / (HH / RR);
    const int d    = p % DD;
    const int b    = p / DD;

    const size_t HW = (size_t)HH * WW;
    const size_t sp = (size_t)hb * WW + w0;
    float* o0 = out + ((size_t)(b * 3 + 0) * DD + d) * HW + sp;
    float* o1 = out + ((size_t)(b * 3 + 1) * DD + d) * HW + sp;
    float* o2 = out + ((size_t)(b * 3 + 2) * DD + d) * HW + sp;
    float* oy = out + (size_t)3 * BB * DD * HW + ((size_t)(b * DD + d)) * HW + sp;

    // ---- trivial path: d = 0 or D-1 can never be a strict 26-neighbour maximum
    // (replicate padding makes the clamped d-neighbour equal x0), so offsets are 0
    // and y_max = x exactly. Pure streaming copy + constant coords.
    if (d == 0 || d == DD - 1) {
        const float* pl1 = x + ((size_t)(b * DD + d) * HH) * WW + sp;
        const float fd = (float)d;
        const float4 c0q = make_float4(fd, fd, fd, fd);
        const float4 c1q = make_float4((float)w0, (float)(w0 + 1), (float)(w0 + 2), (float)(w0 + 3));
        #pragma unroll
        for (int r = 0; r < RR; r++) {
            const float fh = (float)(hb + r);
            float4 xv = *reinterpret_cast<const float4*>(pl1 + (size_t)r * WW);
            __stcs(reinterpret_cast<float4*>(o0 + (size_t)r * WW), c0q);
            __stcs(reinterpret_cast<float4*>(o1 + (size_t)r * WW), c1q);
            __stcs(reinterpret_cast<float4*>(o2 + (size_t)r * WW), make_float4(fh, fh, fh, fh));
            __stcs(reinterpret_cast<float4*>(oy + (size_t)r * WW), xv);
        }
        return;
    }

    // ---- stencil path: d in {1, 2}, all three d-planes are real (no clamping) ----
    const float* pl0 = x + ((size_t)(b * DD + (d - 1)) * HH) * WW;
    const float* pl1 = x + ((size_t)(b * DD + d      ) * HH) * WW;
    const float* pl2 = x + ((size_t)(b * DD + (d + 1)) * HH) * WW;

    float v[3][3][6];   // [plane][slot][k]
    float rm9[3][6];    // per-slot 3-plane column max

    {
        const int ht = (hb == 0) ? 0 : (hb - 1);
        load_row6(pl0 + (size_t)ht * WW, w0, lane, v[0][0]);
        load_row6(pl1 + (size_t)ht * WW, w0, lane, v[1][0]);
        load_row6(pl2 + (size_t)ht * WW, w0, lane, v[2][0]);
        load_row6(pl0 + (size_t)hb * WW, w0, lane, v[0][1]);
        load_row6(pl1 + (size_t)hb * WW, w0, lane, v[1][1]);
        load_row6(pl2 + (size_t)hb * WW, w0, lane, v[2][1]);
        #pragma unroll
        for (int k = 0; k < 6; k++) {
            rm9[0][k] = fmaxf(fmaxf(v[0][0][k], v[1][0][k]), v[2][0][k]);
            rm9[1][k] = fmaxf(fmaxf(v[0][1][k], v[1][1][k]), v[2][1][k]);
        }
    }

    #pragma unroll
    for (int r = 0; r < RR; r++) {
        const int st = r % 3;
        const int sm = (r + 1) % 3;
        const int sb = (r + 2) % 3;
        const int h  = hb + r;

        {
            const int hn = (h + 1 >= HH) ? (HH - 1) : (h + 1);
            load_row6(pl0 + (size_t)hn * WW, w0, lane, v[0][sb]);
            load_row6(pl1 + (size_t)hn * WW, w0, lane, v[1][sb]);
            load_row6(pl2 + (size_t)hn * WW, w0, lane, v[2][sb]);
            #pragma unroll
            for (int k = 0; k < 6; k++)
                rm9[sb][k] = fmaxf(fmaxf(v[0][sb][k], v[1][sb][k]), v[2][sb][k]);
        }

        // ---- NMS (separable): vm = vertical max of top/bottom slot maxima ----
        float vm[6];
        #pragma unroll
        for (int k = 0; k < 6; k++) vm[k] = fmaxf(rm9[st][k], rm9[sb][k]);

        bool nmsq[4];
        unsigned bal[4];
        #pragma unroll
        for (int j = 0; j < 4; j++) {
            const int c = j + 1;
            float nb = fmaxf(vm[c - 1], vm[c]);
            nb = fmaxf(nb, vm[c + 1]);
            nb = fmaxf(nb, rm9[sm][c - 1]);
            nb = fmaxf(nb, rm9[sm][c + 1]);
            nb = fmaxf(nb, fmaxf(v[0][sm][c], v[2][sm][c]));
            nb = fmaxf(nb, 0.0f);
            nmsq[j] = (v[1][sm][c] > nb);
            bal[j] = __ballot_sync(0xffffffffu, nmsq[j]);
        }

        // ---- shared row differences (CSE for gy/dxy and gs/dys/dxs) ----
        float diffbt[6], d20sm[6];
        #pragma unroll
        for (int k = 0; k < 6; k++) {
            diffbt[k] = v[1][sb][k] - v[1][st][k];
            d20sm[k]  = v[2][sm][k] - v[0][sm][k];
        }

        float oc0[4], oc1[4], oc2[4], oyv[4];
        const float fh = (float)h;

        #pragma unroll
        for (int j = 0; j < 4; j++) {
            const int c = j + 1;
            const float x0 = v[1][sm][c];

            if (bal[j]) {   // warp-uniform: at least one lane is a strict maximum
                const float gx = 0.5f * (v[1][sm][c + 1] - v[1][sm][c - 1]);
                const float gy = 0.5f * diffbt[c];
                const float gs = 0.5f * d20sm[c];

                const float dxx = v[1][sm][c + 1] + v[1][sm][c - 1] - 2.0f * x0;
                const float dyy = v[1][sb][c]     + v[1][st][c]     - 2.0f * x0;
                const float dss = v[2][sm][c]     + v[0][sm][c]     - 2.0f * x0;

                const float dxy =  0.25f * (diffbt[c + 1] - diffbt[c - 1]);
                const float dys = -0.25f * ((v[2][sb][c] - v[0][sb][c]) - (v[2][st][c] - v[0][st][c]));
                const float dxs = -0.25f * (d20sm[c + 1] - d20sm[c - 1]);

                const float cf00 = dyy * dss - dys * dys;
                const float cf01 = dxy * dss - dys * dxs;
                const float cf02 = dxy * dys - dyy * dxs;
                const float det  = dxx * cf00 - dxy * cf01 + dxs * cf02;
                const bool solved = (det != 0.0f);
                float inv;
                asm("rcp.approx.f32 %0, %1;" : "=f"(inv) : "f"(solved ? det : 1.0f));

                const float t0 = gy * dss - dys * gs;
                const float t1 = gy * dys - dyy * gs;
                const float t2 = dxy * gs - gy * dxs;

                const float sx = (gx  * cf00 - dxy * t0   + dxs * t1) * inv;
                const float sy = (dxx * t0   - gx  * cf01 + dxs * t2) * inv;
                const float ss = (-dxx * t1  - dxy * t2   + gx  * cf02) * inv;

                const bool valid = nmsq[j] && solved;
                const float amax = fmaxf(fmaxf(fabsf(sx), fabsf(sy)), fabsf(ss));
                const bool keep = valid && (amax <= 0.7f);

                oc0[j] = (float)d + (keep ? -ss : 0.0f);
                oc1[j] = (float)(w0 + j) + (keep ? -sx : 0.0f);
                oc2[j] = fh + (keep ? -sy : 0.0f);

                float ym = valid ? (x0 + 10.0f) : x0;
                if (keep) {
                    const float t = fmaf(gx, sx, fmaf(gy, sy, gs * ss));
                    ym = fmaf(-0.5f, t, ym);
                }
                oyv[j] = ym;
            } else {        // no maximum anywhere in this warp column: trivial output
                oc0[j] = (float)d;
                oc1[j] = (float)(w0 + j);
                oc2[j] = fh;
                oyv[j] = x0;
            }
        }

        __stcs(reinterpret_cast<float4*>(o0 + (size_t)r * WW), make_float4(oc0[0], oc0[1], oc0[2], oc0[3]));
        __stcs(reinterpret_cast<float4*>(o1 + (size_t)r * WW), make_float4(oc1[0], oc1[1], oc1[2], oc1[3]));
        __stcs(reinterpret_cast<float4*>(o2 + (size_t)r * WW), make_float4(oc2[0], oc2[1], oc2[2], oc2[3]));
        __stcs(reinterpret_cast<float4*>(oy + (size_t)r * WW), make_float4(oyv[0], oyv[1], oyv[2], oyv[3]));
    }
}

extern "C" void kernel_launch(void* const* d_in, const int* in_sizes, int n_in,
                              void* d_out, int out_size) {
    const float* x = (const float*)d_in[0];
    float* out = (float*)d_out;
    dim3 grid(BB * DD * (HH / RR));  // 3072 blocks
    dim3 block(192);
    cqi3d_kernel<<<grid, block>>>(x, out);
}